// round 5
// baseline (speedup 1.0000x reference)
#include <cuda_runtime.h>
#include <math_constants.h>

// Problem constants
#define NN    8192
#define CI    128      // IN_DIM == HID
#define HID   128
#define HEADS 4
#define HD    32
#define OUTD  40
#define RSQRT_HD 0.17677669529663687f  // 1/sqrt(32)

// ---------------- scratch (device globals; no allocation allowed) -------------
__device__ float g_h  [NN * HID];       // h = x@W_in^T + b_in
__device__ float g_qkv[NN * 3 * HID];   // qkv
__device__ float g_ao [NN * HID];       // attention output (N, HEADS*HD)
__device__ float g_h2 [NN * HID];       // h + relu(out_proj)

// ---------------- generic GEMM: C[M,CO] = A[M,128] @ W[CO,128]^T + b ----------
// optional epilogue: C = R + relu(C)   (residual add, R stride == CO)
// Tile: 64 rows x 64 cols per CTA, 256 threads, 4x4 microtile.
// A and W staged through smem and transposed for conflict-free vector reads.

#define GEMM_SMEM_FLOATS (2*128*64 + 64*132)   // At + Wt + staging
#define GEMM_SMEM_BYTES  (GEMM_SMEM_FLOATS * 4)

__global__ __launch_bounds__(256, 2)
void gemm_k(const float* __restrict__ A, const float* __restrict__ W,
            const float* __restrict__ bias, const float* __restrict__ R,
            float* __restrict__ C, int M, int CO, int relu_res)
{
    extern __shared__ float sm[];
    float* At  = sm;                 // [128][64] transposed A tile
    float* Wt  = sm + 128*64;        // [128][64] transposed W tile
    float* Stg = sm + 2*128*64;      // [64][132] staging

    const int r0  = blockIdx.x * 64;
    const int c0  = blockIdx.y * 64;
    const int tid = threadIdx.x;

    // ---- stage A (coalesced) ----
    {
        const float4* Af4 = (const float4*)(A + (size_t)r0 * CI);
        float4* Sf4 = (float4*)Stg;
        #pragma unroll
        for (int i = 0; i < 8; i++) {
            int idx = tid + 256*i;          // 2048 float4s
            int r = idx >> 5, d4 = idx & 31;
            Sf4[r*33 + d4] = Af4[r*32 + d4];
        }
    }
    __syncthreads();
    // ---- transpose A -> At[d][r] ----
    {
        #pragma unroll
        for (int i = 0; i < 8; i++) {
            int idx = tid + 256*i;
            int r = idx & 63, d4 = idx >> 6;
            float4 v = *(const float4*)&Stg[r*132 + d4*4];
            At[(4*d4+0)*64 + r] = v.x;
            At[(4*d4+1)*64 + r] = v.y;
            At[(4*d4+2)*64 + r] = v.z;
            At[(4*d4+3)*64 + r] = v.w;
        }
    }
    __syncthreads();
    // ---- stage W (bounds-guarded, zero fill) ----
    {
        const float4* Wf4 = (const float4*)W;
        float4* Sf4 = (float4*)Stg;
        #pragma unroll
        for (int i = 0; i < 8; i++) {
            int idx = tid + 256*i;
            int c = idx >> 5, d4 = idx & 31;
            float4 v = make_float4(0.f, 0.f, 0.f, 0.f);
            if (c0 + c < CO) v = Wf4[(size_t)(c0 + c)*32 + d4];
            Sf4[c*33 + d4] = v;
        }
    }
    __syncthreads();
    // ---- transpose W -> Wt[d][c] ----
    {
        #pragma unroll
        for (int i = 0; i < 8; i++) {
            int idx = tid + 256*i;
            int c = idx & 63, d4 = idx >> 6;
            float4 v = *(const float4*)&Stg[c*132 + d4*4];
            Wt[(4*d4+0)*64 + c] = v.x;
            Wt[(4*d4+1)*64 + c] = v.y;
            Wt[(4*d4+2)*64 + c] = v.z;
            Wt[(4*d4+3)*64 + c] = v.w;
        }
    }
    __syncthreads();

    // ---- compute 4x4 microtile ----
    const int tr = tid >> 4;   // 0..15  -> rows tr*4..tr*4+3
    const int tc = tid & 15;   // 0..15  -> cols tc*4..tc*4+3
    float acc[4][4];
    #pragma unroll
    for (int i = 0; i < 4; i++)
        #pragma unroll
        for (int j = 0; j < 4; j++) acc[i][j] = 0.f;

    #pragma unroll 8
    for (int d = 0; d < 128; d++) {
        float4 a = *(const float4*)&At[d*64 + tr*4];
        float4 w = *(const float4*)&Wt[d*64 + tc*4];
        float av[4] = {a.x, a.y, a.z, a.w};
        float wv[4] = {w.x, w.y, w.z, w.w};
        #pragma unroll
        for (int i = 0; i < 4; i++)
            #pragma unroll
            for (int j = 0; j < 4; j++)
                acc[i][j] = fmaf(av[i], wv[j], acc[i][j]);
    }

    // ---- epilogue ----
    #pragma unroll
    for (int i = 0; i < 4; i++) {
        int r = r0 + tr*4 + i;
        #pragma unroll
        for (int j = 0; j < 4; j++) {
            int c = c0 + tc*4 + j;
            if (c < CO) {
                float v = acc[i][j] + bias[c];
                if (relu_res) v = R[(size_t)r*CO + c] + fmaxf(v, 0.f);
                C[(size_t)r*CO + c] = v;
            }
        }
    }
}

// ---------------- fused flash attention (fp32, online softmax) ----------------
// grid = N/64 CTAs, 256 threads. Thread t: head = t>>6, query-in-block = t&63.
// All 4 heads handled in one CTA so the sp/bias tile is read ONCE from HBM.
// Smem: K tile [4][64][8]f4 (32KB), V tile same (32KB), bias [64k][67] (17KB).

#define BM 64
#define BN 64
#define ATTN_SMEM_BYTES (2*2048*16 + 64*67*4)

__device__ __forceinline__ float bias_of(float s, float scale)
{
    if (isnan(s) || isinf(s)) s = -1.0f;       // nan_to_num(sp, -1)
    float t = 1.0f / s;                         // 1/0 -> inf
    if (isnan(t) || isinf(t)) t = 0.0f;         // nan_to_num(1/sp, 0)
    return scale * t;
}

__global__ __launch_bounds__(256, 1)
void attn_k(const float* __restrict__ qkv, const float* __restrict__ sp,
            const float* __restrict__ scale_ptr, float* __restrict__ out)
{
    extern __shared__ float sm[];
    float4* Ksh = (float4*)sm;           // [head][j][u]  head*512 + j*8 + u
    float4* Vsh = Ksh + 2048;
    float*  Bsh = (float*)(Vsh + 2048);  // [j][qi], stride 67

    const int tid  = threadIdx.x;
    const int head = tid >> 6;
    const int qi   = tid & 63;
    const int q0   = blockIdx.x * BM;
    const float scale = scale_ptr[0];

    const float4* qkvf4 = (const float4*)qkv;   // row stride 96 f4
    const float4* spf4  = (const float4*)sp;    // row stride 2048 f4

    // load this thread's query row (HD=32 floats) into registers
    float4 q[8];
    #pragma unroll
    for (int u = 0; u < 8; u++)
        q[u] = qkvf4[(size_t)(q0 + qi)*96 + head*8 + u];

    float4 o[8];
    #pragma unroll
    for (int u = 0; u < 8; u++) o[u] = make_float4(0.f, 0.f, 0.f, 0.f);
    float m = -CUDART_INF_F, l = 0.f;

    for (int kb = 0; kb < NN / BN; kb++) {
        const int k0 = kb * BN;
        // ---- load K/V tiles (all heads), coalesced ----
        #pragma unroll
        for (int i = 0; i < 8; i++) {
            int idx = tid + 256*i;          // 2048 f4 per tile
            int j = idx >> 5, c = idx & 31;
            int dst = (c >> 3)*512 + j*8 + (c & 7);
            Ksh[dst] = qkvf4[(size_t)(k0 + j)*96 + 32 + c];
            Vsh[dst] = qkvf4[(size_t)(k0 + j)*96 + 64 + c];
        }
        // ---- load + transform bias tile, store transposed [key][query] ----
        #pragma unroll
        for (int i = 0; i < 4; i++) {
            int idx = tid + 256*i;          // 1024 f4
            int qq = idx >> 4, c4 = idx & 15;
            float4 s4 = spf4[(size_t)(q0 + qq)*2048 + kb*16 + c4];
            Bsh[(4*c4+0)*67 + qq] = bias_of(s4.x, scale);
            Bsh[(4*c4+1)*67 + qq] = bias_of(s4.y, scale);
            Bsh[(4*c4+2)*67 + qq] = bias_of(s4.z, scale);
            Bsh[(4*c4+3)*67 + qq] = bias_of(s4.w, scale);
        }
        __syncthreads();

        const float4* Kh = Ksh + head*512;
        const float4* Vh = Vsh + head*512;

        #pragma unroll
        for (int jc = 0; jc < 4; jc++) {      // 4 chunks of 16 keys
            float sv[16];
            float cm = -CUDART_INF_F;
            #pragma unroll
            for (int jj = 0; jj < 16; jj++) {
                int j = jc*16 + jj;
                const float4* kp = Kh + j*8;
                float acc = 0.f;
                #pragma unroll
                for (int u = 0; u < 8; u++) {
                    float4 k4 = kp[u];
                    acc = fmaf(q[u].x, k4.x, acc);
                    acc = fmaf(q[u].y, k4.y, acc);
                    acc = fmaf(q[u].z, k4.z, acc);
                    acc = fmaf(q[u].w, k4.w, acc);
                }
                float s = fmaf(acc, RSQRT_HD, Bsh[j*67 + qi]);
                sv[jj] = s;
                cm = fmaxf(cm, s);
            }
            if (cm > m) {
                float corr = __expf(m - cm);   // first block: exp(-inf)=0
                l *= corr;
                #pragma unroll
                for (int u = 0; u < 8; u++) {
                    o[u].x *= corr; o[u].y *= corr; o[u].z *= corr; o[u].w *= corr;
                }
                m = cm;
            }
            #pragma unroll
            for (int jj = 0; jj < 16; jj++) {
                float p = __expf(sv[jj] - m);
                l += p;
                const float4* vp = Vh + (jc*16 + jj)*8;
                #pragma unroll
                for (int u = 0; u < 8; u++) {
                    float4 v4 = vp[u];
                    o[u].x = fmaf(p, v4.x, o[u].x);
                    o[u].y = fmaf(p, v4.y, o[u].y);
                    o[u].z = fmaf(p, v4.z, o[u].z);
                    o[u].w = fmaf(p, v4.w, o[u].w);
                }
            }
        }
        __syncthreads();
    }

    const float inv = 1.0f / l;
    float4* of4 = (float4*)out;                 // row stride 32 f4
    #pragma unroll
    for (int u = 0; u < 8; u++) {
        float4 t;
        t.x = o[u].x * inv; t.y = o[u].y * inv;
        t.z = o[u].z * inv; t.w = o[u].w * inv;
        of4[(size_t)(q0 + qi)*32 + head*8 + u] = t;
    }
}

// ---------------- log_softmax over last dim (40), in-place ----------------
__global__ __launch_bounds__(256)
void logsoftmax_k(float* __restrict__ io)
{
    int row  = blockIdx.x * 8 + (threadIdx.x >> 5);
    int lane = threadIdx.x & 31;
    float* p = io + (size_t)row * OUTD;

    float a = p[lane];
    float b = (lane < 8) ? p[lane + 32] : -CUDART_INF_F;

    float mx = fmaxf(a, b);
    #pragma unroll
    for (int off = 16; off; off >>= 1)
        mx = fmaxf(mx, __shfl_xor_sync(0xffffffffu, mx, off));

    float e = __expf(a - mx) + ((lane < 8) ? __expf(b - mx) : 0.f);
    #pragma unroll
    for (int off = 16; off; off >>= 1)
        e += __shfl_xor_sync(0xffffffffu, e, off);

    float lse = mx + logf(e);
    p[lane] = a - lse;
    if (lane < 8) p[lane + 32] = b - lse;
}

// ---------------- launch ----------------
extern "C" void kernel_launch(void* const* d_in, const int* in_sizes, int n_in,
                              void* d_out, int out_size)
{
    (void)in_sizes; (void)n_in; (void)out_size;
    const float* x     = (const float*)d_in[0];
    // d_in[1] = pos_enc, unused in forward (faithful to reference)
    const float* sp    = (const float*)d_in[2];
    const float* W_in  = (const float*)d_in[3];
    const float* b_in  = (const float*)d_in[4];
    const float* ipw   = (const float*)d_in[5];
    const float* ipb   = (const float*)d_in[6];
    const float* opw   = (const float*)d_in[7];
    const float* opb   = (const float*)d_in[8];
    const float* Wout  = (const float*)d_in[9];
    const float* bout  = (const float*)d_in[10];
    const float* scale = (const float*)d_in[11];
    float* out = (float*)d_out;

    float *gh, *gqkv, *gao, *gh2;
    cudaGetSymbolAddress((void**)&gh,   g_h);
    cudaGetSymbolAddress((void**)&gqkv, g_qkv);
    cudaGetSymbolAddress((void**)&gao,  g_ao);
    cudaGetSymbolAddress((void**)&gh2,  g_h2);

    cudaFuncSetAttribute(gemm_k, cudaFuncAttributeMaxDynamicSharedMemorySize, GEMM_SMEM_BYTES);
    cudaFuncSetAttribute(attn_k, cudaFuncAttributeMaxDynamicSharedMemorySize, ATTN_SMEM_BYTES);

    // h = x @ W_in^T + b_in
    gemm_k<<<dim3(NN/64, 2), 256, GEMM_SMEM_BYTES>>>(x, W_in, b_in, nullptr, gh, NN, HID, 0);
    // qkv = h @ in_proj_w^T + in_proj_b
    gemm_k<<<dim3(NN/64, 6), 256, GEMM_SMEM_BYTES>>>(gh, ipw, ipb, nullptr, gqkv, NN, 3*HID, 0);
    // attention (bias computed inline from sp)
    attn_k<<<NN/BM, 256, ATTN_SMEM_BYTES>>>(gqkv, sp, scale, gao);
    // h2 = h + relu(ao @ out_proj^T + out_proj_b)
    gemm_k<<<dim3(NN/64, 2), 256, GEMM_SMEM_BYTES>>>(gao, opw, opb, gh, gh2, NN, HID, 1);
    // logits = h2 @ W_out^T + b_out  (written straight to d_out)
    gemm_k<<<dim3(NN/64, 1), 256, GEMM_SMEM_BYTES>>>(gh2, Wout, bout, nullptr, out, NN, OUTD, 0);
    // log_softmax in-place
    logsoftmax_k<<<NN/8, 256>>>(out);
}

// round 6
// speedup vs baseline: 5.9546x; 5.9546x over previous
#include <cuda_runtime.h>
#include <cuda_bf16.h>
#include <math_constants.h>
#include <cstdint>

// Problem constants
#define NN    8192
#define HID   128
#define HEADS 4
#define HD    32
#define OUTD  40
#define RSQRT_HD 0.17677669529663687f  // 1/sqrt(32)
#define L2E      1.4426950408889634f

// ---------------- scratch (device globals) ----------------
__device__ float          g_h  [NN * HID];   // h = x@W_in^T + b_in (fp32 residual)
__device__ __nv_bfloat16  g_qb [NN * HID];   // Q * rsqrt(hd), bf16 [token][h*32+d]
__device__ __nv_bfloat16  g_kb [NN * HID];   // K bf16 [token][h*32+d]
__device__ __nv_bfloat16  g_vt [HID * NN];   // V bf16 transposed [h*32+d][token]
__device__ float          g_ao [NN * HID];   // attention output
__device__ float          g_h2 [NN * HID];   // h + relu(out_proj)

// ---------------- small asm helpers ----------------
__device__ __forceinline__ uint32_t smem_u32(const void* p){
    uint32_t a;
    asm("{ .reg .u64 t; cvta.to.shared.u64 t, %1; cvt.u32.u64 %0, t; }" : "=r"(a) : "l"(p));
    return a;
}
__device__ __forceinline__ void ldsm4(uint32_t r[4], uint32_t addr){
    asm volatile("ldmatrix.sync.aligned.m8n8.x4.shared.b16 {%0,%1,%2,%3}, [%4];"
        : "=r"(r[0]), "=r"(r[1]), "=r"(r[2]), "=r"(r[3]) : "r"(addr));
}
__device__ __forceinline__ void mma16816(float c[4], const uint32_t a[4], const uint32_t b[2]){
    asm volatile("mma.sync.aligned.m16n8k16.row.col.f32.bf16.bf16.f32 "
        "{%0,%1,%2,%3}, {%4,%5,%6,%7}, {%8,%9}, {%0,%1,%2,%3};"
        : "+f"(c[0]), "+f"(c[1]), "+f"(c[2]), "+f"(c[3])
        : "r"(a[0]), "r"(a[1]), "r"(a[2]), "r"(a[3]), "r"(b[0]), "r"(b[1]));
}
__device__ __forceinline__ float ex2f(float x){
    float r; asm("ex2.approx.f32 %0, %1;" : "=f"(r) : "f"(x)); return r;
}
__device__ __forceinline__ uint32_t packbf(float hi, float lo){
    uint32_t r; asm("cvt.rn.bf16x2.f32 %0, %1, %2;" : "=r"(r) : "f"(hi), "f"(lo)); return r;
}

// bias2 = (scale * nan_to_num(1/nan_to_num(sp,-1), 0) - m) * log2(e)
__device__ __forceinline__ float bias2_of(float s, float scale, float nml2e){
    if (isnan(s) || isinf(s)) s = -1.0f;
    float r = __fdividef(1.0f, s);            // 1/0 -> +inf
    if (isnan(r) || isinf(r)) r = 0.0f;
    return fmaf(scale * r, L2E, nml2e);       // (scale*r - m)*L2E
}

// ---------------- GEMM: C[M,CO] = A[M,128] @ W[CO,128]^T + b ----------------
// mode 0: plain fp32 ; mode 1: C = R + relu(.) ; mode 2: qkv -> bf16 Q/K/Vt
#define GEMM_SMEM_FLOATS (2*128*64 + 64*132)
#define GEMM_SMEM_BYTES  (GEMM_SMEM_FLOATS * 4)

__global__ __launch_bounds__(256, 2)
void gemm_k(const float* __restrict__ A, const float* __restrict__ W,
            const float* __restrict__ bias, const float* __restrict__ R,
            float* __restrict__ C, int CO, int mode,
            __nv_bfloat16* __restrict__ qb, __nv_bfloat16* __restrict__ kb,
            __nv_bfloat16* __restrict__ vt)
{
    extern __shared__ float sm[];
    float* At  = sm;
    float* Wt  = sm + 128*64;
    float* Stg = sm + 2*128*64;

    const int r0  = blockIdx.x * 64;
    const int c0  = blockIdx.y * 64;
    const int tid = threadIdx.x;

    {   // stage A
        const float4* Af4 = (const float4*)(A + (size_t)r0 * 128);
        float4* Sf4 = (float4*)Stg;
        #pragma unroll
        for (int i = 0; i < 8; i++) {
            int idx = tid + 256*i;
            int r = idx >> 5, d4 = idx & 31;
            Sf4[r*33 + d4] = Af4[r*32 + d4];
        }
    }
    __syncthreads();
    {   // transpose A
        #pragma unroll
        for (int i = 0; i < 8; i++) {
            int idx = tid + 256*i;
            int r = idx & 63, d4 = idx >> 6;
            float4 v = *(const float4*)&Stg[r*132 + d4*4];
            At[(4*d4+0)*64 + r] = v.x; At[(4*d4+1)*64 + r] = v.y;
            At[(4*d4+2)*64 + r] = v.z; At[(4*d4+3)*64 + r] = v.w;
        }
    }
    __syncthreads();
    {   // stage W
        const float4* Wf4 = (const float4*)W;
        float4* Sf4 = (float4*)Stg;
        #pragma unroll
        for (int i = 0; i < 8; i++) {
            int idx = tid + 256*i;
            int c = idx >> 5, d4 = idx & 31;
            float4 v = make_float4(0.f,0.f,0.f,0.f);
            if (c0 + c < CO) v = Wf4[(size_t)(c0 + c)*32 + d4];
            Sf4[c*33 + d4] = v;
        }
    }
    __syncthreads();
    {   // transpose W
        #pragma unroll
        for (int i = 0; i < 8; i++) {
            int idx = tid + 256*i;
            int c = idx & 63, d4 = idx >> 6;
            float4 v = *(const float4*)&Stg[c*132 + d4*4];
            Wt[(4*d4+0)*64 + c] = v.x; Wt[(4*d4+1)*64 + c] = v.y;
            Wt[(4*d4+2)*64 + c] = v.z; Wt[(4*d4+3)*64 + c] = v.w;
        }
    }
    __syncthreads();

    const int tr = tid >> 4;
    const int tc = tid & 15;
    float acc[4][4];
    #pragma unroll
    for (int i = 0; i < 4; i++)
        #pragma unroll
        for (int j = 0; j < 4; j++) acc[i][j] = 0.f;

    #pragma unroll 8
    for (int d = 0; d < 128; d++) {
        float4 a = *(const float4*)&At[d*64 + tr*4];
        float4 w = *(const float4*)&Wt[d*64 + tc*4];
        float av[4] = {a.x, a.y, a.z, a.w};
        float wv[4] = {w.x, w.y, w.z, w.w};
        #pragma unroll
        for (int i = 0; i < 4; i++)
            #pragma unroll
            for (int j = 0; j < 4; j++)
                acc[i][j] = fmaf(av[i], wv[j], acc[i][j]);
    }

    #pragma unroll
    for (int i = 0; i < 4; i++) {
        int r = r0 + tr*4 + i;
        #pragma unroll
        for (int j = 0; j < 4; j++) {
            int c = c0 + tc*4 + j;
            if (c < CO) {
                float v = acc[i][j] + bias[c];
                if (mode == 2) {
                    if (c < 128)      qb[(size_t)r*128 + c]       = __float2bfloat16(v * RSQRT_HD);
                    else if (c < 256) kb[(size_t)r*128 + (c-128)] = __float2bfloat16(v);
                    else              vt[(size_t)(c-256)*NN + r]  = __float2bfloat16(v);
                } else {
                    if (mode == 1) v = R[(size_t)r*128 + c] + fmaxf(v, 0.f);
                    C[(size_t)r*CO + c] = v;
                }
            }
        }
    }
}

// ---------------- tensor-core flash attention ----------------
// CTA: 32 queries x ALL 4 heads x all 8192 keys (64-key blocks).
// 8 warps: warp w -> head w>>1, query m16-tile (w&1)*16.
// Smem (single-buffered):
//   Ks: [64 keys][16 chunks of 16B]  stride 272B   (also used to stage Q)
//   Vs: [128 rows = h*32+d][64 keys] stride 144B
//   Bs: [32 q][64 k] fp32 bias2      stride 288B
#define KS_OFF   0
#define VS_OFF   17408
#define BS_OFF   35840
#define ATTN_SMEM 45056

__global__ __launch_bounds__(256, 2)
void attn_k(const __nv_bfloat16* __restrict__ qb_g, const __nv_bfloat16* __restrict__ kb_g,
            const __nv_bfloat16* __restrict__ vt_g, const float* __restrict__ sp,
            const float* __restrict__ scale_ptr, float* __restrict__ out)
{
    extern __shared__ char smc[];
    const uint32_t sb = smem_u32(smc);
    const int tid  = threadIdx.x;
    const int lane = tid & 31;
    const int wid  = tid >> 5;
    const int h    = wid >> 1;
    const int qbo  = (wid & 1) * 16;
    const int q0   = blockIdx.x * 32;

    const float scale = scale_ptr[0];
    const float nml2e = -(scale + 8.0f) * L2E;    // -(m)*log2e, m = scale+8

    // ---- stage Q (32 rows x 256B) into Ks region, build A fragments ----
    {
        const uint4* qsrc = (const uint4*)(qb_g + (size_t)q0 * 128);
        #pragma unroll
        for (int i = 0; i < 2; i++) {
            int idx = tid + 256*i;
            int r = idx >> 4, c = idx & 15;
            *(uint4*)(smc + KS_OFF + r*272 + c*16) = qsrc[r*16 + c];
        }
    }
    __syncthreads();
    uint32_t qa[2][4];
    {
        uint32_t qaddr = sb + KS_OFF + (qbo + (lane & 15))*272 + (h*4 + (lane >> 4))*16;
        ldsm4(qa[0], qaddr);
        ldsm4(qa[1], qaddr + 32);
    }
    __syncthreads();

    // loop-invariant per-lane ldsm/lds addresses
    const uint32_t kaddr = sb + KS_OFF + ((lane & 7) + ((lane >> 4) & 1)*8)*272
                           + h*64 + ((lane >> 3) & 1)*16;
    const uint32_t vaddr = sb + VS_OFF + (h*32 + (lane & 7) + ((lane >> 4) & 1)*8)*144
                           + ((lane >> 3) & 1)*16;
    const uint32_t baddr = sb + BS_OFF + (qbo + (lane >> 2))*288 + (lane & 3)*8;

    float O[4][4];
    #pragma unroll
    for (int i = 0; i < 4; i++)
        #pragma unroll
        for (int j = 0; j < 4; j++) O[i][j] = 0.f;
    float l0 = 0.f, l1 = 0.f;

    const uint4* ksrc = (const uint4*)kb_g;   // row = 16 uint4
    const uint4* vsrc = (const uint4*)vt_g;   // row = 1024 uint4

    for (int kb = 0; kb < NN/64; kb++) {
        const int k0 = kb * 64;
        // ---- load K tile ----
        #pragma unroll
        for (int i = 0; i < 4; i++) {
            int idx = tid + 256*i;
            int r = idx >> 4, c = idx & 15;
            *(uint4*)(smc + KS_OFF + r*272 + c*16) = ksrc[(size_t)(k0 + r)*16 + c];
        }
        // ---- load V^T tile ----
        #pragma unroll
        for (int i = 0; i < 4; i++) {
            int idx = tid + 256*i;
            int r = idx >> 3, c = idx & 7;
            *(uint4*)(smc + VS_OFF + r*144 + c*16) = vsrc[(size_t)r*1024 + (k0 >> 3) + c];
        }
        // ---- load + transform bias tile ----
        #pragma unroll
        for (int i = 0; i < 2; i++) {
            int idx = tid + 256*i;
            int qq = idx >> 4, c4 = idx & 15;
            float4 s4 = *(const float4*)(sp + (size_t)(q0 + qq)*NN + k0 + c4*4);
            float4 b4;
            b4.x = bias2_of(s4.x, scale, nml2e);
            b4.y = bias2_of(s4.y, scale, nml2e);
            b4.z = bias2_of(s4.z, scale, nml2e);
            b4.w = bias2_of(s4.w, scale, nml2e);
            *(float4*)(smc + BS_OFF + qq*288 + c4*16) = b4;
        }
        __syncthreads();

        // ---- S = Q K^T  (1 m-tile x 8 n-tiles x 2 k-steps) ----
        float S[8][4];
        #pragma unroll
        for (int j = 0; j < 8; j++)
            #pragma unroll
            for (int t = 0; t < 4; t++) S[j][t] = 0.f;
        #pragma unroll
        for (int s = 0; s < 2; s++) {
            #pragma unroll
            for (int p = 0; p < 4; p++) {      // n-tile pairs
                uint32_t kbf[4];
                ldsm4(kbf, kaddr + p*(16*272) + s*32);
                mma16816(S[2*p],   qa[s], kbf);
                mma16816(S[2*p+1], qa[s], kbf + 2);
            }
        }

        // ---- softmax (fixed shift), pack P to bf16 A-fragments ----
        uint32_t pk[4][4];
        #pragma unroll
        for (int j = 0; j < 8; j++) {
            float b0, b1, b2, b3;
            asm volatile("ld.shared.v2.f32 {%0,%1}, [%2];"
                         : "=f"(b0), "=f"(b1) : "r"(baddr + j*32));
            asm volatile("ld.shared.v2.f32 {%0,%1}, [%2];"
                         : "=f"(b2), "=f"(b3) : "r"(baddr + j*32 + 8*288));
            float p0 = ex2f(fmaf(S[j][0], L2E, b0));
            float p1 = ex2f(fmaf(S[j][1], L2E, b1));
            float p2 = ex2f(fmaf(S[j][2], L2E, b2));
            float p3 = ex2f(fmaf(S[j][3], L2E, b3));
            l0 += p0 + p1;
            l1 += p2 + p3;
            int s = j >> 1, o = (j & 1) * 2;
            pk[s][o]     = packbf(p1, p0);
            pk[s][o + 1] = packbf(p3, p2);
        }

        // ---- O += P V  (4 k-steps x 4 d-tiles) ----
        #pragma unroll
        for (int s = 0; s < 4; s++) {
            uint32_t vb[8];
            ldsm4(vb,     vaddr + s*32);              // d-tiles 0,1
            ldsm4(vb + 4, vaddr + 16*144 + s*32);     // d-tiles 2,3
            mma16816(O[0], pk[s], vb);
            mma16816(O[1], pk[s], vb + 2);
            mma16816(O[2], pk[s], vb + 4);
            mma16816(O[3], pk[s], vb + 6);
        }
        __syncthreads();
    }

    // ---- finalize: row sums across quads, normalize, store ----
    l0 += __shfl_xor_sync(0xffffffffu, l0, 1);
    l0 += __shfl_xor_sync(0xffffffffu, l0, 2);
    l1 += __shfl_xor_sync(0xffffffffu, l1, 1);
    l1 += __shfl_xor_sync(0xffffffffu, l1, 2);
    const float i0 = 1.0f / l0;
    const float i1 = 1.0f / l1;

    const int r  = q0 + qbo + (lane >> 2);
    const int cb = h*32 + 2*(lane & 3);
    #pragma unroll
    for (int j = 0; j < 4; j++) {
        float2 v0 = make_float2(O[j][0]*i0, O[j][1]*i0);
        float2 v1 = make_float2(O[j][2]*i1, O[j][3]*i1);
        *(float2*)(out + (size_t)r*128 + cb + 8*j)       = v0;
        *(float2*)(out + (size_t)(r+8)*128 + cb + 8*j)   = v1;
    }
}

// ---------------- log_softmax over last dim (40), in-place ----------------
__global__ __launch_bounds__(256)
void logsoftmax_k(float* __restrict__ io)
{
    int row  = blockIdx.x * 8 + (threadIdx.x >> 5);
    int lane = threadIdx.x & 31;
    float* p = io + (size_t)row * OUTD;

    float a = p[lane];
    float b = (lane < 8) ? p[lane + 32] : -CUDART_INF_F;

    float mx = fmaxf(a, b);
    #pragma unroll
    for (int off = 16; off; off >>= 1)
        mx = fmaxf(mx, __shfl_xor_sync(0xffffffffu, mx, off));

    float e = __expf(a - mx) + ((lane < 8) ? __expf(b - mx) : 0.f);
    #pragma unroll
    for (int off = 16; off; off >>= 1)
        e += __shfl_xor_sync(0xffffffffu, e, off);

    float lse = mx + logf(e);
    p[lane] = a - lse;
    if (lane < 8) p[lane + 32] = b - lse;
}

// ---------------- launch ----------------
extern "C" void kernel_launch(void* const* d_in, const int* in_sizes, int n_in,
                              void* d_out, int out_size)
{
    (void)in_sizes; (void)n_in; (void)out_size;
    const float* x     = (const float*)d_in[0];
    // d_in[1] = pos_enc, unused in forward (faithful to reference)
    const float* sp    = (const float*)d_in[2];
    const float* W_in  = (const float*)d_in[3];
    const float* b_in  = (const float*)d_in[4];
    const float* ipw   = (const float*)d_in[5];
    const float* ipb   = (const float*)d_in[6];
    const float* opw   = (const float*)d_in[7];
    const float* opb   = (const float*)d_in[8];
    const float* Wout  = (const float*)d_in[9];
    const float* bout  = (const float*)d_in[10];
    const float* scale = (const float*)d_in[11];
    float* out = (float*)d_out;

    float *gh, *gao, *gh2;
    __nv_bfloat16 *gqb, *gkb, *gvt;
    cudaGetSymbolAddress((void**)&gh,  g_h);
    cudaGetSymbolAddress((void**)&gao, g_ao);
    cudaGetSymbolAddress((void**)&gh2, g_h2);
    cudaGetSymbolAddress((void**)&gqb, g_qb);
    cudaGetSymbolAddress((void**)&gkb, g_kb);
    cudaGetSymbolAddress((void**)&gvt, g_vt);

    cudaFuncSetAttribute(gemm_k, cudaFuncAttributeMaxDynamicSharedMemorySize, GEMM_SMEM_BYTES);
    cudaFuncSetAttribute(attn_k, cudaFuncAttributeMaxDynamicSharedMemorySize, ATTN_SMEM);

    // h = x @ W_in^T + b_in
    gemm_k<<<dim3(NN/64, 2), 256, GEMM_SMEM_BYTES>>>(x, W_in, b_in, nullptr, gh, HID, 0,
                                                     nullptr, nullptr, nullptr);
    // qkv = h @ in_proj_w^T + b  -> bf16 Q (pre-scaled), K, V^T
    gemm_k<<<dim3(NN/64, 6), 256, GEMM_SMEM_BYTES>>>(gh, ipw, ipb, nullptr, nullptr, 3*HID, 2,
                                                     gqb, gkb, gvt);
    // tensor-core flash attention
    attn_k<<<NN/32, 256, ATTN_SMEM>>>(gqb, gkb, gvt, sp, scale, gao);
    // h2 = h + relu(ao @ out_proj^T + b)
    gemm_k<<<dim3(NN/64, 2), 256, GEMM_SMEM_BYTES>>>(gao, opw, opb, gh, gh2, HID, 1,
                                                     nullptr, nullptr, nullptr);
    // logits = h2 @ W_out^T + b_out
    gemm_k<<<dim3(NN/64, 1), 256, GEMM_SMEM_BYTES>>>(gh2, Wout, bout, nullptr, out, OUTD, 0,
                                                     nullptr, nullptr, nullptr);
    // log_softmax in-place
    logsoftmax_k<<<NN/8, 256>>>(out);
}

// round 7
// speedup vs baseline: 5.9999x; 1.0076x over previous
#include <cuda_runtime.h>
#include <cuda_bf16.h>
#include <math_constants.h>
#include <cstdint>

// Problem constants
#define NN    8192
#define HID   128
#define HEADS 4
#define HD    32
#define OUTD  40
#define RSQRT_HD 0.17677669529663687f  // 1/sqrt(32)
#define L2E      1.4426950408889634f

// ---------------- scratch (device globals) ----------------
__device__ float          g_h  [NN * HID];   // h = x@W_in^T + b_in (fp32 residual)
__device__ __nv_bfloat16  g_qb [NN * HID];   // Q * rsqrt(hd), bf16 [token][h*32+d]
__device__ __nv_bfloat16  g_kb [NN * HID];   // K bf16 [token][h*32+d]
__device__ __nv_bfloat16  g_vt [HID * NN];   // V bf16 transposed [h*32+d][token]
__device__ float          g_ao [NN * HID];   // attention output
__device__ float          g_h2 [NN * HID];   // h + relu(out_proj)

// ---------------- small asm helpers ----------------
__device__ __forceinline__ uint32_t smem_u32(const void* p){
    uint32_t a;
    asm("{ .reg .u64 t; cvta.to.shared.u64 t, %1; cvt.u32.u64 %0, t; }" : "=r"(a) : "l"(p));
    return a;
}
__device__ __forceinline__ void ldsm4(uint32_t r[4], uint32_t addr){
    asm volatile("ldmatrix.sync.aligned.m8n8.x4.shared.b16 {%0,%1,%2,%3}, [%4];"
        : "=r"(r[0]), "=r"(r[1]), "=r"(r[2]), "=r"(r[3]) : "r"(addr));
}
__device__ __forceinline__ void mma16816(float c[4], const uint32_t a[4], const uint32_t b[2]){
    asm volatile("mma.sync.aligned.m16n8k16.row.col.f32.bf16.bf16.f32 "
        "{%0,%1,%2,%3}, {%4,%5,%6,%7}, {%8,%9}, {%0,%1,%2,%3};"
        : "+f"(c[0]), "+f"(c[1]), "+f"(c[2]), "+f"(c[3])
        : "r"(a[0]), "r"(a[1]), "r"(a[2]), "r"(a[3]), "r"(b[0]), "r"(b[1]));
}
__device__ __forceinline__ float ex2f(float x){
    float r; asm("ex2.approx.f32 %0, %1;" : "=f"(r) : "f"(x)); return r;
}
__device__ __forceinline__ uint32_t packbf(float hi, float lo){
    uint32_t r; asm("cvt.rn.bf16x2.f32 %0, %1, %2;" : "=r"(r) : "f"(hi), "f"(lo)); return r;
}

// bias2 = (scale * nan_to_num(1/nan_to_num(sp,-1), 0) - m) * log2(e)
__device__ __forceinline__ float bias2_of(float s, float scale, float nml2e){
    if (isnan(s) || isinf(s)) s = -1.0f;
    float r = __fdividef(1.0f, s);            // 1/0 -> +inf
    if (isnan(r) || isinf(r)) r = 0.0f;
    return fmaf(scale * r, L2E, nml2e);       // (scale*r - m)*L2E
}

// ---------------- GEMM: C[M,CO] = A[M,128] @ W[CO,128]^T + b ----------------
// mode 0: plain fp32 ; mode 1: C = R + relu(.) ; mode 2: qkv -> bf16 Q/K/Vt
#define GEMM_SMEM_FLOATS (2*128*64 + 64*132)
#define GEMM_SMEM_BYTES  (GEMM_SMEM_FLOATS * 4)

__global__ __launch_bounds__(256, 2)
void gemm_k(const float* __restrict__ A, const float* __restrict__ W,
            const float* __restrict__ bias, const float* __restrict__ R,
            float* __restrict__ C, int CO, int mode,
            __nv_bfloat16* __restrict__ qb, __nv_bfloat16* __restrict__ kb,
            __nv_bfloat16* __restrict__ vt)
{
    extern __shared__ float sm[];
    float* At  = sm;
    float* Wt  = sm + 128*64;
    float* Stg = sm + 2*128*64;

    const int r0  = blockIdx.x * 64;
    const int c0  = blockIdx.y * 64;
    const int tid = threadIdx.x;

    {   // stage A
        const float4* Af4 = (const float4*)(A + (size_t)r0 * 128);
        float4* Sf4 = (float4*)Stg;
        #pragma unroll
        for (int i = 0; i < 8; i++) {
            int idx = tid + 256*i;
            int r = idx >> 5, d4 = idx & 31;
            Sf4[r*33 + d4] = Af4[r*32 + d4];
        }
    }
    __syncthreads();
    {   // transpose A
        #pragma unroll
        for (int i = 0; i < 8; i++) {
            int idx = tid + 256*i;
            int r = idx & 63, d4 = idx >> 6;
            float4 v = *(const float4*)&Stg[r*132 + d4*4];
            At[(4*d4+0)*64 + r] = v.x; At[(4*d4+1)*64 + r] = v.y;
            At[(4*d4+2)*64 + r] = v.z; At[(4*d4+3)*64 + r] = v.w;
        }
    }
    __syncthreads();
    {   // stage W
        const float4* Wf4 = (const float4*)W;
        float4* Sf4 = (float4*)Stg;
        #pragma unroll
        for (int i = 0; i < 8; i++) {
            int idx = tid + 256*i;
            int c = idx >> 5, d4 = idx & 31;
            float4 v = make_float4(0.f,0.f,0.f,0.f);
            if (c0 + c < CO) v = Wf4[(size_t)(c0 + c)*32 + d4];
            Sf4[c*33 + d4] = v;
        }
    }
    __syncthreads();
    {   // transpose W
        #pragma unroll
        for (int i = 0; i < 8; i++) {
            int idx = tid + 256*i;
            int c = idx & 63, d4 = idx >> 6;
            float4 v = *(const float4*)&Stg[c*132 + d4*4];
            Wt[(4*d4+0)*64 + c] = v.x; Wt[(4*d4+1)*64 + c] = v.y;
            Wt[(4*d4+2)*64 + c] = v.z; Wt[(4*d4+3)*64 + c] = v.w;
        }
    }
    __syncthreads();

    const int tr = tid >> 4;
    const int tc = tid & 15;
    float acc[4][4];
    #pragma unroll
    for (int i = 0; i < 4; i++)
        #pragma unroll
        for (int j = 0; j < 4; j++) acc[i][j] = 0.f;

    #pragma unroll 8
    for (int d = 0; d < 128; d++) {
        float4 a = *(const float4*)&At[d*64 + tr*4];
        float4 w = *(const float4*)&Wt[d*64 + tc*4];
        float av[4] = {a.x, a.y, a.z, a.w};
        float wv[4] = {w.x, w.y, w.z, w.w};
        #pragma unroll
        for (int i = 0; i < 4; i++)
            #pragma unroll
            for (int j = 0; j < 4; j++)
                acc[i][j] = fmaf(av[i], wv[j], acc[i][j]);
    }

    #pragma unroll
    for (int i = 0; i < 4; i++) {
        int r = r0 + tr*4 + i;
        #pragma unroll
        for (int j = 0; j < 4; j++) {
            int c = c0 + tc*4 + j;
            if (c < CO) {
                float v = acc[i][j] + bias[c];
                if (mode == 2) {
                    if (c < 128)      qb[(size_t)r*128 + c]       = __float2bfloat16(v * RSQRT_HD);
                    else if (c < 256) kb[(size_t)r*128 + (c-128)] = __float2bfloat16(v);
                    else              vt[(size_t)(c-256)*NN + r]  = __float2bfloat16(v);
                } else {
                    if (mode == 1) v = R[(size_t)r*128 + c] + fmaxf(v, 0.f);
                    C[(size_t)r*CO + c] = v;
                }
            }
        }
    }
}

// ---------------- tensor-core flash attention ----------------
// CTA: 32 queries x ALL 4 heads x all 8192 keys (64-key blocks).
// 8 warps: warp w -> head w>>1, query m16-tile (w&1)*16.
// Smem (single-buffered):
//   Ks: [64 keys][16 chunks of 16B]  stride 272B   (also used to stage Q)
//   Vs: [128 rows = h*32+d][64 keys] stride 144B
//   Bs: [32 q][64 k] fp32 bias2      stride 288B
#define KS_OFF   0
#define VS_OFF   17408
#define BS_OFF   35840
#define ATTN_SMEM 45056

__global__ __launch_bounds__(256, 2)
void attn_k(const __nv_bfloat16* __restrict__ qb_g, const __nv_bfloat16* __restrict__ kb_g,
            const __nv_bfloat16* __restrict__ vt_g, const float* __restrict__ sp,
            const float* __restrict__ scale_ptr, float* __restrict__ out)
{
    extern __shared__ char smc[];
    const uint32_t sb = smem_u32(smc);
    const int tid  = threadIdx.x;
    const int lane = tid & 31;
    const int wid  = tid >> 5;
    const int h    = wid >> 1;
    const int qbo  = (wid & 1) * 16;
    const int q0   = blockIdx.x * 32;

    const float scale = scale_ptr[0];
    const float nml2e = -(scale + 8.0f) * L2E;    // -(m)*log2e, m = scale+8

    // ---- stage Q (32 rows x 256B) into Ks region, build A fragments ----
    {
        const uint4* qsrc = (const uint4*)(qb_g + (size_t)q0 * 128);
        #pragma unroll
        for (int i = 0; i < 2; i++) {
            int idx = tid + 256*i;
            int r = idx >> 4, c = idx & 15;
            *(uint4*)(smc + KS_OFF + r*272 + c*16) = qsrc[r*16 + c];
        }
    }
    __syncthreads();
    uint32_t qa[2][4];
    {
        uint32_t qaddr = sb + KS_OFF + (qbo + (lane & 15))*272 + (h*4 + (lane >> 4))*16;
        ldsm4(qa[0], qaddr);
        ldsm4(qa[1], qaddr + 32);
    }
    __syncthreads();

    // loop-invariant per-lane ldsm/lds addresses
    const uint32_t kaddr = sb + KS_OFF + ((lane & 7) + ((lane >> 4) & 1)*8)*272
                           + h*64 + ((lane >> 3) & 1)*16;
    const uint32_t vaddr = sb + VS_OFF + (h*32 + (lane & 7) + ((lane >> 4) & 1)*8)*144
                           + ((lane >> 3) & 1)*16;
    const uint32_t baddr = sb + BS_OFF + (qbo + (lane >> 2))*288 + (lane & 3)*8;

    float O[4][4];
    #pragma unroll
    for (int i = 0; i < 4; i++)
        #pragma unroll
        for (int j = 0; j < 4; j++) O[i][j] = 0.f;
    float l0 = 0.f, l1 = 0.f;

    const uint4* ksrc = (const uint4*)kb_g;   // row = 16 uint4
    const uint4* vsrc = (const uint4*)vt_g;   // row = 1024 uint4

    for (int kb = 0; kb < NN/64; kb++) {
        const int k0 = kb * 64;
        // ---- load K tile ----
        #pragma unroll
        for (int i = 0; i < 4; i++) {
            int idx = tid + 256*i;
            int r = idx >> 4, c = idx & 15;
            *(uint4*)(smc + KS_OFF + r*272 + c*16) = ksrc[(size_t)(k0 + r)*16 + c];
        }
        // ---- load V^T tile ----
        #pragma unroll
        for (int i = 0; i < 4; i++) {
            int idx = tid + 256*i;
            int r = idx >> 3, c = idx & 7;
            *(uint4*)(smc + VS_OFF + r*144 + c*16) = vsrc[(size_t)r*1024 + (k0 >> 3) + c];
        }
        // ---- load + transform bias tile ----
        #pragma unroll
        for (int i = 0; i < 2; i++) {
            int idx = tid + 256*i;
            int qq = idx >> 4, c4 = idx & 15;
            float4 s4 = *(const float4*)(sp + (size_t)(q0 + qq)*NN + k0 + c4*4);
            float4 b4;
            b4.x = bias2_of(s4.x, scale, nml2e);
            b4.y = bias2_of(s4.y, scale, nml2e);
            b4.z = bias2_of(s4.z, scale, nml2e);
            b4.w = bias2_of(s4.w, scale, nml2e);
            *(float4*)(smc + BS_OFF + qq*288 + c4*16) = b4;
        }
        __syncthreads();

        // ---- S = Q K^T  (1 m-tile x 8 n-tiles x 2 k-steps) ----
        float S[8][4];
        #pragma unroll
        for (int j = 0; j < 8; j++)
            #pragma unroll
            for (int t = 0; t < 4; t++) S[j][t] = 0.f;
        #pragma unroll
        for (int s = 0; s < 2; s++) {
            #pragma unroll
            for (int p = 0; p < 4; p++) {      // n-tile pairs
                uint32_t kbf[4];
                ldsm4(kbf, kaddr + p*(16*272) + s*32);
                mma16816(S[2*p],   qa[s], kbf);
                mma16816(S[2*p+1], qa[s], kbf + 2);
            }
        }

        // ---- softmax (fixed shift), pack P to bf16 A-fragments ----
        uint32_t pk[4][4];
        #pragma unroll
        for (int j = 0; j < 8; j++) {
            float b0, b1, b2, b3;
            asm volatile("ld.shared.v2.f32 {%0,%1}, [%2];"
                         : "=f"(b0), "=f"(b1) : "r"(baddr + j*32));
            asm volatile("ld.shared.v2.f32 {%0,%1}, [%2];"
                         : "=f"(b2), "=f"(b3) : "r"(baddr + j*32 + 8*288));
            float p0 = ex2f(fmaf(S[j][0], L2E, b0));
            float p1 = ex2f(fmaf(S[j][1], L2E, b1));
            float p2 = ex2f(fmaf(S[j][2], L2E, b2));
            float p3 = ex2f(fmaf(S[j][3], L2E, b3));
            l0 += p0 + p1;
            l1 += p2 + p3;
            int s = j >> 1, o = (j & 1) * 2;
            pk[s][o]     = packbf(p1, p0);
            pk[s][o + 1] = packbf(p3, p2);
        }

        // ---- O += P V  (4 k-steps x 4 d-tiles) ----
        #pragma unroll
        for (int s = 0; s < 4; s++) {
            uint32_t vb[8];
            ldsm4(vb,     vaddr + s*32);              // d-tiles 0,1
            ldsm4(vb + 4, vaddr + 16*144 + s*32);     // d-tiles 2,3
            mma16816(O[0], pk[s], vb);
            mma16816(O[1], pk[s], vb + 2);
            mma16816(O[2], pk[s], vb + 4);
            mma16816(O[3], pk[s], vb + 6);
        }
        __syncthreads();
    }

    // ---- finalize: row sums across quads, normalize, store ----
    l0 += __shfl_xor_sync(0xffffffffu, l0, 1);
    l0 += __shfl_xor_sync(0xffffffffu, l0, 2);
    l1 += __shfl_xor_sync(0xffffffffu, l1, 1);
    l1 += __shfl_xor_sync(0xffffffffu, l1, 2);
    const float i0 = 1.0f / l0;
    const float i1 = 1.0f / l1;

    const int r  = q0 + qbo + (lane >> 2);
    const int cb = h*32 + 2*(lane & 3);
    #pragma unroll
    for (int j = 0; j < 4; j++) {
        float2 v0 = make_float2(O[j][0]*i0, O[j][1]*i0);
        float2 v1 = make_float2(O[j][2]*i1, O[j][3]*i1);
        *(float2*)(out + (size_t)r*128 + cb + 8*j)       = v0;
        *(float2*)(out + (size_t)(r+8)*128 + cb + 8*j)   = v1;
    }
}

// ---------------- log_softmax over last dim (40), in-place ----------------
__global__ __launch_bounds__(256)
void logsoftmax_k(float* __restrict__ io)
{
    int row  = blockIdx.x * 8 + (threadIdx.x >> 5);
    int lane = threadIdx.x & 31;
    float* p = io + (size_t)row * OUTD;

    float a = p[lane];
    float b = (lane < 8) ? p[lane + 32] : -CUDART_INF_F;

    float mx = fmaxf(a, b);
    #pragma unroll
    for (int off = 16; off; off >>= 1)
        mx = fmaxf(mx, __shfl_xor_sync(0xffffffffu, mx, off));

    float e = __expf(a - mx) + ((lane < 8) ? __expf(b - mx) : 0.f);
    #pragma unroll
    for (int off = 16; off; off >>= 1)
        e += __shfl_xor_sync(0xffffffffu, e, off);

    float lse = mx + logf(e);
    p[lane] = a - lse;
    if (lane < 8) p[lane + 32] = b - lse;
}

// ---------------- launch ----------------
extern "C" void kernel_launch(void* const* d_in, const int* in_sizes, int n_in,
                              void* d_out, int out_size)
{
    (void)in_sizes; (void)n_in; (void)out_size;
    const float* x     = (const float*)d_in[0];
    // d_in[1] = pos_enc, unused in forward (faithful to reference)
    const float* sp    = (const float*)d_in[2];
    const float* W_in  = (const float*)d_in[3];
    const float* b_in  = (const float*)d_in[4];
    const float* ipw   = (const float*)d_in[5];
    const float* ipb   = (const float*)d_in[6];
    const float* opw   = (const float*)d_in[7];
    const float* opb   = (const float*)d_in[8];
    const float* Wout  = (const float*)d_in[9];
    const float* bout  = (const float*)d_in[10];
    const float* scale = (const float*)d_in[11];
    float* out = (float*)d_out;

    float *gh, *gao, *gh2;
    __nv_bfloat16 *gqb, *gkb, *gvt;
    cudaGetSymbolAddress((void**)&gh,  g_h);
    cudaGetSymbolAddress((void**)&gao, g_ao);
    cudaGetSymbolAddress((void**)&gh2, g_h2);
    cudaGetSymbolAddress((void**)&gqb, g_qb);
    cudaGetSymbolAddress((void**)&gkb, g_kb);
    cudaGetSymbolAddress((void**)&gvt, g_vt);

    cudaFuncSetAttribute(gemm_k, cudaFuncAttributeMaxDynamicSharedMemorySize, GEMM_SMEM_BYTES);
    cudaFuncSetAttribute(attn_k, cudaFuncAttributeMaxDynamicSharedMemorySize, ATTN_SMEM);

    // h = x @ W_in^T + b_in
    gemm_k<<<dim3(NN/64, 2), 256, GEMM_SMEM_BYTES>>>(x, W_in, b_in, nullptr, gh, HID, 0,
                                                     nullptr, nullptr, nullptr);
    // qkv = h @ in_proj_w^T + b  -> bf16 Q (pre-scaled), K, V^T
    gemm_k<<<dim3(NN/64, 6), 256, GEMM_SMEM_BYTES>>>(gh, ipw, ipb, nullptr, nullptr, 3*HID, 2,
                                                     gqb, gkb, gvt);
    // tensor-core flash attention
    attn_k<<<NN/32, 256, ATTN_SMEM>>>(gqb, gkb, gvt, sp, scale, gao);
    // h2 = h + relu(ao @ out_proj^T + b)
    gemm_k<<<dim3(NN/64, 2), 256, GEMM_SMEM_BYTES>>>(gao, opw, opb, gh, gh2, HID, 1,
                                                     nullptr, nullptr, nullptr);
    // logits = h2 @ W_out^T + b_out
    gemm_k<<<dim3(NN/64, 1), 256, GEMM_SMEM_BYTES>>>(gh2, Wout, bout, nullptr, out, OUTD, 0,
                                                     nullptr, nullptr, nullptr);
    // log_softmax in-place
    logsoftmax_k<<<NN/8, 256>>>(out);
}

// round 8
// speedup vs baseline: 6.0303x; 1.0051x over previous
#include <cuda_runtime.h>
#include <cuda_bf16.h>
#include <math_constants.h>
#include <cstdint>

// Problem constants
#define NN    8192
#define HID   128
#define HEADS 4
#define HD    32
#define OUTD  40
#define RSQRT_HD 0.17677669529663687f  // 1/sqrt(32)
#define L2E      1.4426950408889634f

// ---------------- scratch (device globals) ----------------
__device__ float          g_h  [NN * HID];   // h = x@W_in^T + b_in (fp32 residual)
__device__ __nv_bfloat16  g_qb [NN * HID];   // Q * rsqrt(hd), bf16 [token][h*32+d]
__device__ __nv_bfloat16  g_kb [NN * HID];   // K bf16 [token][h*32+d]
__device__ __nv_bfloat16  g_vt [HID * NN];   // V bf16 transposed [h*32+d][token]
__device__ float          g_ao [NN * HID];   // attention output
__device__ float          g_h2 [NN * HID];   // h + relu(out_proj)

// ---------------- small asm helpers ----------------
__device__ __forceinline__ uint32_t smem_u32(const void* p){
    uint32_t a;
    asm("{ .reg .u64 t; cvta.to.shared.u64 t, %1; cvt.u32.u64 %0, t; }" : "=r"(a) : "l"(p));
    return a;
}
__device__ __forceinline__ void ldsm4(uint32_t r[4], uint32_t addr){
    asm volatile("ldmatrix.sync.aligned.m8n8.x4.shared.b16 {%0,%1,%2,%3}, [%4];"
        : "=r"(r[0]), "=r"(r[1]), "=r"(r[2]), "=r"(r[3]) : "r"(addr));
}
__device__ __forceinline__ void mma16816(float c[4], const uint32_t a[4], const uint32_t b[2]){
    asm volatile("mma.sync.aligned.m16n8k16.row.col.f32.bf16.bf16.f32 "
        "{%0,%1,%2,%3}, {%4,%5,%6,%7}, {%8,%9}, {%0,%1,%2,%3};"
        : "+f"(c[0]), "+f"(c[1]), "+f"(c[2]), "+f"(c[3])
        : "r"(a[0]), "r"(a[1]), "r"(a[2]), "r"(a[3]), "r"(b[0]), "r"(b[1]));
}
__device__ __forceinline__ float ex2f(float x){
    float r; asm("ex2.approx.f32 %0, %1;" : "=f"(r) : "f"(x)); return r;
}
__device__ __forceinline__ uint32_t packbf(float hi, float lo){
    uint32_t r; asm("cvt.rn.bf16x2.f32 %0, %1, %2;" : "=r"(r) : "f"(hi), "f"(lo)); return r;
}

// bias2 = (scale * nan_to_num(1/nan_to_num(sp,-1), 0) - m) * log2(e)
__device__ __forceinline__ float bias2_of(float s, float scale, float nml2e){
    if (isnan(s) || isinf(s)) s = -1.0f;
    float r = __fdividef(1.0f, s);            // 1/0 -> +inf
    if (isnan(r) || isinf(r)) r = 0.0f;
    return fmaf(scale * r, L2E, nml2e);       // (scale*r - m)*L2E
}

// ---------------- GEMM: C[M,CO] = A[M,128] @ W[CO,128]^T + b ----------------
// mode 0: plain fp32 ; mode 1: C = R + relu(.) ; mode 2: qkv -> bf16 Q/K/Vt
#define GEMM_SMEM_FLOATS (2*128*64 + 64*132)
#define GEMM_SMEM_BYTES  (GEMM_SMEM_FLOATS * 4)

__global__ __launch_bounds__(256, 2)
void gemm_k(const float* __restrict__ A, const float* __restrict__ W,
            const float* __restrict__ bias, const float* __restrict__ R,
            float* __restrict__ C, int CO, int mode,
            __nv_bfloat16* __restrict__ qb, __nv_bfloat16* __restrict__ kb,
            __nv_bfloat16* __restrict__ vt)
{
    extern __shared__ float sm[];
    float* At  = sm;
    float* Wt  = sm + 128*64;
    float* Stg = sm + 2*128*64;

    const int r0  = blockIdx.x * 64;
    const int c0  = blockIdx.y * 64;
    const int tid = threadIdx.x;

    {   // stage A
        const float4* Af4 = (const float4*)(A + (size_t)r0 * 128);
        float4* Sf4 = (float4*)Stg;
        #pragma unroll
        for (int i = 0; i < 8; i++) {
            int idx = tid + 256*i;
            int r = idx >> 5, d4 = idx & 31;
            Sf4[r*33 + d4] = Af4[r*32 + d4];
        }
    }
    __syncthreads();
    {   // transpose A
        #pragma unroll
        for (int i = 0; i < 8; i++) {
            int idx = tid + 256*i;
            int r = idx & 63, d4 = idx >> 6;
            float4 v = *(const float4*)&Stg[r*132 + d4*4];
            At[(4*d4+0)*64 + r] = v.x; At[(4*d4+1)*64 + r] = v.y;
            At[(4*d4+2)*64 + r] = v.z; At[(4*d4+3)*64 + r] = v.w;
        }
    }
    __syncthreads();
    {   // stage W
        const float4* Wf4 = (const float4*)W;
        float4* Sf4 = (float4*)Stg;
        #pragma unroll
        for (int i = 0; i < 8; i++) {
            int idx = tid + 256*i;
            int c = idx >> 5, d4 = idx & 31;
            float4 v = make_float4(0.f,0.f,0.f,0.f);
            if (c0 + c < CO) v = Wf4[(size_t)(c0 + c)*32 + d4];
            Sf4[c*33 + d4] = v;
        }
    }
    __syncthreads();
    {   // transpose W
        #pragma unroll
        for (int i = 0; i < 8; i++) {
            int idx = tid + 256*i;
            int c = idx & 63, d4 = idx >> 6;
            float4 v = *(const float4*)&Stg[c*132 + d4*4];
            Wt[(4*d4+0)*64 + c] = v.x; Wt[(4*d4+1)*64 + c] = v.y;
            Wt[(4*d4+2)*64 + c] = v.z; Wt[(4*d4+3)*64 + c] = v.w;
        }
    }
    __syncthreads();

    const int tr = tid >> 4;
    const int tc = tid & 15;
    float acc[4][4];
    #pragma unroll
    for (int i = 0; i < 4; i++)
        #pragma unroll
        for (int j = 0; j < 4; j++) acc[i][j] = 0.f;

    #pragma unroll 8
    for (int d = 0; d < 128; d++) {
        float4 a = *(const float4*)&At[d*64 + tr*4];
        float4 w = *(const float4*)&Wt[d*64 + tc*4];
        float av[4] = {a.x, a.y, a.z, a.w};
        float wv[4] = {w.x, w.y, w.z, w.w};
        #pragma unroll
        for (int i = 0; i < 4; i++)
            #pragma unroll
            for (int j = 0; j < 4; j++)
                acc[i][j] = fmaf(av[i], wv[j], acc[i][j]);
    }

    #pragma unroll
    for (int i = 0; i < 4; i++) {
        int r = r0 + tr*4 + i;
        #pragma unroll
        for (int j = 0; j < 4; j++) {
            int c = c0 + tc*4 + j;
            if (c < CO) {
                float v = acc[i][j] + bias[c];
                if (mode == 2) {
                    if (c < 128)      qb[(size_t)r*128 + c]       = __float2bfloat16(v * RSQRT_HD);
                    else if (c < 256) kb[(size_t)r*128 + (c-128)] = __float2bfloat16(v);
                    else              vt[(size_t)(c-256)*NN + r]  = __float2bfloat16(v);
                } else {
                    if (mode == 1) v = R[(size_t)r*128 + c] + fmaxf(v, 0.f);
                    C[(size_t)r*CO + c] = v;
                }
            }
        }
    }
}

// ---------------- tensor-core flash attention ----------------
// CTA: 32 queries x ALL 4 heads x all 8192 keys (64-key blocks).
// 8 warps: warp w -> head w>>1, query m16-tile (w&1)*16.
// Smem (single-buffered):
//   Ks: [64 keys][16 chunks of 16B]  stride 272B   (also used to stage Q)
//   Vs: [128 rows = h*32+d][64 keys] stride 144B
//   Bs: [32 q][64 k] fp32 bias2      stride 288B
#define KS_OFF   0
#define VS_OFF   17408
#define BS_OFF   35840
#define ATTN_SMEM 45056

__global__ __launch_bounds__(256, 2)
void attn_k(const __nv_bfloat16* __restrict__ qb_g, const __nv_bfloat16* __restrict__ kb_g,
            const __nv_bfloat16* __restrict__ vt_g, const float* __restrict__ sp,
            const float* __restrict__ scale_ptr, float* __restrict__ out)
{
    extern __shared__ char smc[];
    const uint32_t sb = smem_u32(smc);
    const int tid  = threadIdx.x;
    const int lane = tid & 31;
    const int wid  = tid >> 5;
    const int h    = wid >> 1;
    const int qbo  = (wid & 1) * 16;
    const int q0   = blockIdx.x * 32;

    const float scale = scale_ptr[0];
    const float nml2e = -(scale + 8.0f) * L2E;    // -(m)*log2e, m = scale+8

    // ---- stage Q (32 rows x 256B) into Ks region, build A fragments ----
    {
        const uint4* qsrc = (const uint4*)(qb_g + (size_t)q0 * 128);
        #pragma unroll
        for (int i = 0; i < 2; i++) {
            int idx = tid + 256*i;
            int r = idx >> 4, c = idx & 15;
            *(uint4*)(smc + KS_OFF + r*272 + c*16) = qsrc[r*16 + c];
        }
    }
    __syncthreads();
    uint32_t qa[2][4];
    {
        uint32_t qaddr = sb + KS_OFF + (qbo + (lane & 15))*272 + (h*4 + (lane >> 4))*16;
        ldsm4(qa[0], qaddr);
        ldsm4(qa[1], qaddr + 32);
    }
    __syncthreads();

    // loop-invariant per-lane ldsm/lds addresses
    const uint32_t kaddr = sb + KS_OFF + ((lane & 7) + ((lane >> 4) & 1)*8)*272
                           + h*64 + ((lane >> 3) & 1)*16;
    const uint32_t vaddr = sb + VS_OFF + (h*32 + (lane & 7) + ((lane >> 4) & 1)*8)*144
                           + ((lane >> 3) & 1)*16;
    const uint32_t baddr = sb + BS_OFF + (qbo + (lane >> 2))*288 + (lane & 3)*8;

    float O[4][4];
    #pragma unroll
    for (int i = 0; i < 4; i++)
        #pragma unroll
        for (int j = 0; j < 4; j++) O[i][j] = 0.f;
    float l0 = 0.f, l1 = 0.f;

    const uint4* ksrc = (const uint4*)kb_g;   // row = 16 uint4
    const uint4* vsrc = (const uint4*)vt_g;   // row = 1024 uint4

    for (int kb = 0; kb < NN/64; kb++) {
        const int k0 = kb * 64;
        // ---- load K tile ----
        #pragma unroll
        for (int i = 0; i < 4; i++) {
            int idx = tid + 256*i;
            int r = idx >> 4, c = idx & 15;
            *(uint4*)(smc + KS_OFF + r*272 + c*16) = ksrc[(size_t)(k0 + r)*16 + c];
        }
        // ---- load V^T tile ----
        #pragma unroll
        for (int i = 0; i < 4; i++) {
            int idx = tid + 256*i;
            int r = idx >> 3, c = idx & 7;
            *(uint4*)(smc + VS_OFF + r*144 + c*16) = vsrc[(size_t)r*1024 + (k0 >> 3) + c];
        }
        // ---- load + transform bias tile ----
        #pragma unroll
        for (int i = 0; i < 2; i++) {
            int idx = tid + 256*i;
            int qq = idx >> 4, c4 = idx & 15;
            float4 s4 = *(const float4*)(sp + (size_t)(q0 + qq)*NN + k0 + c4*4);
            float4 b4;
            b4.x = bias2_of(s4.x, scale, nml2e);
            b4.y = bias2_of(s4.y, scale, nml2e);
            b4.z = bias2_of(s4.z, scale, nml2e);
            b4.w = bias2_of(s4.w, scale, nml2e);
            *(float4*)(smc + BS_OFF + qq*288 + c4*16) = b4;
        }
        __syncthreads();

        // ---- S = Q K^T  (1 m-tile x 8 n-tiles x 2 k-steps) ----
        float S[8][4];
        #pragma unroll
        for (int j = 0; j < 8; j++)
            #pragma unroll
            for (int t = 0; t < 4; t++) S[j][t] = 0.f;
        #pragma unroll
        for (int s = 0; s < 2; s++) {
            #pragma unroll
            for (int p = 0; p < 4; p++) {      // n-tile pairs
                uint32_t kbf[4];
                ldsm4(kbf, kaddr + p*(16*272) + s*32);
                mma16816(S[2*p],   qa[s], kbf);
                mma16816(S[2*p+1], qa[s], kbf + 2);
            }
        }

        // ---- softmax (fixed shift), pack P to bf16 A-fragments ----
        uint32_t pk[4][4];
        #pragma unroll
        for (int j = 0; j < 8; j++) {
            float b0, b1, b2, b3;
            asm volatile("ld.shared.v2.f32 {%0,%1}, [%2];"
                         : "=f"(b0), "=f"(b1) : "r"(baddr + j*32));
            asm volatile("ld.shared.v2.f32 {%0,%1}, [%2];"
                         : "=f"(b2), "=f"(b3) : "r"(baddr + j*32 + 8*288));
            float p0 = ex2f(fmaf(S[j][0], L2E, b0));
            float p1 = ex2f(fmaf(S[j][1], L2E, b1));
            float p2 = ex2f(fmaf(S[j][2], L2E, b2));
            float p3 = ex2f(fmaf(S[j][3], L2E, b3));
            l0 += p0 + p1;
            l1 += p2 + p3;
            int s = j >> 1, o = (j & 1) * 2;
            pk[s][o]     = packbf(p1, p0);
            pk[s][o + 1] = packbf(p3, p2);
        }

        // ---- O += P V  (4 k-steps x 4 d-tiles) ----
        #pragma unroll
        for (int s = 0; s < 4; s++) {
            uint32_t vb[8];
            ldsm4(vb,     vaddr + s*32);              // d-tiles 0,1
            ldsm4(vb + 4, vaddr + 16*144 + s*32);     // d-tiles 2,3
            mma16816(O[0], pk[s], vb);
            mma16816(O[1], pk[s], vb + 2);
            mma16816(O[2], pk[s], vb + 4);
            mma16816(O[3], pk[s], vb + 6);
        }
        __syncthreads();
    }

    // ---- finalize: row sums across quads, normalize, store ----
    l0 += __shfl_xor_sync(0xffffffffu, l0, 1);
    l0 += __shfl_xor_sync(0xffffffffu, l0, 2);
    l1 += __shfl_xor_sync(0xffffffffu, l1, 1);
    l1 += __shfl_xor_sync(0xffffffffu, l1, 2);
    const float i0 = 1.0f / l0;
    const float i1 = 1.0f / l1;

    const int r  = q0 + qbo + (lane >> 2);
    const int cb = h*32 + 2*(lane & 3);
    #pragma unroll
    for (int j = 0; j < 4; j++) {
        float2 v0 = make_float2(O[j][0]*i0, O[j][1]*i0);
        float2 v1 = make_float2(O[j][2]*i1, O[j][3]*i1);
        *(float2*)(out + (size_t)r*128 + cb + 8*j)       = v0;
        *(float2*)(out + (size_t)(r+8)*128 + cb + 8*j)   = v1;
    }
}

// ---------------- log_softmax over last dim (40), in-place ----------------
__global__ __launch_bounds__(256)
void logsoftmax_k(float* __restrict__ io)
{
    int row  = blockIdx.x * 8 + (threadIdx.x >> 5);
    int lane = threadIdx.x & 31;
    float* p = io + (size_t)row * OUTD;

    float a = p[lane];
    float b = (lane < 8) ? p[lane + 32] : -CUDART_INF_F;

    float mx = fmaxf(a, b);
    #pragma unroll
    for (int off = 16; off; off >>= 1)
        mx = fmaxf(mx, __shfl_xor_sync(0xffffffffu, mx, off));

    float e = __expf(a - mx) + ((lane < 8) ? __expf(b - mx) : 0.f);
    #pragma unroll
    for (int off = 16; off; off >>= 1)
        e += __shfl_xor_sync(0xffffffffu, e, off);

    float lse = mx + logf(e);
    p[lane] = a - lse;
    if (lane < 8) p[lane + 32] = b - lse;
}

// ---------------- launch ----------------
extern "C" void kernel_launch(void* const* d_in, const int* in_sizes, int n_in,
                              void* d_out, int out_size)
{
    (void)in_sizes; (void)n_in; (void)out_size;
    const float* x     = (const float*)d_in[0];
    // d_in[1] = pos_enc, unused in forward (faithful to reference)
    const float* sp    = (const float*)d_in[2];
    const float* W_in  = (const float*)d_in[3];
    const float* b_in  = (const float*)d_in[4];
    const float* ipw   = (const float*)d_in[5];
    const float* ipb   = (const float*)d_in[6];
    const float* opw   = (const float*)d_in[7];
    const float* opb   = (const float*)d_in[8];
    const float* Wout  = (const float*)d_in[9];
    const float* bout  = (const float*)d_in[10];
    const float* scale = (const float*)d_in[11];
    float* out = (float*)d_out;

    float *gh, *gao, *gh2;
    __nv_bfloat16 *gqb, *gkb, *gvt;
    cudaGetSymbolAddress((void**)&gh,  g_h);
    cudaGetSymbolAddress((void**)&gao, g_ao);
    cudaGetSymbolAddress((void**)&gh2, g_h2);
    cudaGetSymbolAddress((void**)&gqb, g_qb);
    cudaGetSymbolAddress((void**)&gkb, g_kb);
    cudaGetSymbolAddress((void**)&gvt, g_vt);

    cudaFuncSetAttribute(gemm_k, cudaFuncAttributeMaxDynamicSharedMemorySize, GEMM_SMEM_BYTES);
    cudaFuncSetAttribute(attn_k, cudaFuncAttributeMaxDynamicSharedMemorySize, ATTN_SMEM);

    // h = x @ W_in^T + b_in
    gemm_k<<<dim3(NN/64, 2), 256, GEMM_SMEM_BYTES>>>(x, W_in, b_in, nullptr, gh, HID, 0,
                                                     nullptr, nullptr, nullptr);
    // qkv = h @ in_proj_w^T + b  -> bf16 Q (pre-scaled), K, V^T
    gemm_k<<<dim3(NN/64, 6), 256, GEMM_SMEM_BYTES>>>(gh, ipw, ipb, nullptr, nullptr, 3*HID, 2,
                                                     gqb, gkb, gvt);
    // tensor-core flash attention
    attn_k<<<NN/32, 256, ATTN_SMEM>>>(gqb, gkb, gvt, sp, scale, gao);
    // h2 = h + relu(ao @ out_proj^T + b)
    gemm_k<<<dim3(NN/64, 2), 256, GEMM_SMEM_BYTES>>>(gao, opw, opb, gh, gh2, HID, 1,
                                                     nullptr, nullptr, nullptr);
    // logits = h2 @ W_out^T + b_out
    gemm_k<<<dim3(NN/64, 1), 256, GEMM_SMEM_BYTES>>>(gh2, Wout, bout, nullptr, out, OUTD, 0,
                                                     nullptr, nullptr, nullptr);
    // log_softmax in-place
    logsoftmax_k<<<NN/8, 256>>>(out);
}